// round 1
// baseline (speedup 1.0000x reference)
#include <cuda_runtime.h>
#include <cstdint>

#define BB 32
#define NN 1024
#define DD 512
#define LN_EPS 1e-5f

// ---------------- scratch (no allocations allowed) ----------------
__device__ float g_denom[BB * NN];           // rowsum + 1
__device__ float g_colsum[BB * NN];
__device__ float g_y[BB * NN * DD];          // Ax + x
__device__ float g_x[BB * NN * DD];          // layer output
__device__ float g_Wt0[DD * DD];             // W0 transposed -> [k][d]
__device__ float g_Wt1[DD * DD];

// ---------------- helpers ----------------
__device__ __forceinline__ float block_reduce_sum(float v, float* sh) {
    __syncthreads();
    int tid = threadIdx.x;
    #pragma unroll
    for (int o = 16; o > 0; o >>= 1) v += __shfl_down_sync(0xffffffff, v, o);
    if ((tid & 31) == 0) sh[tid >> 5] = v;
    __syncthreads();
    if (tid < 32) {
        v = (tid < (int)(blockDim.x >> 5)) ? sh[tid] : 0.0f;
        #pragma unroll
        for (int o = 16; o > 0; o >>= 1) v += __shfl_down_sync(0xffffffff, v, o);
        if (tid == 0) sh[0] = v;
    }
    __syncthreads();
    return sh[0];
}

// ---------------- row sums (denom) ----------------
__global__ void rowsum_kernel(const float* __restrict__ adj, float* __restrict__ denom) {
    __shared__ float sh[32];
    const int row = blockIdx.x;                       // 0 .. B*N-1
    const float* p = adj + (size_t)row * NN;
    float s = 0.0f;
    for (int i = threadIdx.x; i < NN; i += blockDim.x) s += p[i];
    float tot = block_reduce_sum(s, sh);
    if (threadIdx.x == 0) denom[row] = tot + 1.0f;
}

// ---------------- col sums ----------------
__global__ void colsum_kernel(const float* __restrict__ adj, float* __restrict__ colsum) {
    int idx = blockIdx.x * blockDim.x + threadIdx.x;  // b*N + m
    if (idx >= BB * NN) return;
    int b = idx / NN, m = idx % NN;
    const float* p = adj + (size_t)b * NN * NN + m;
    float s = 0.0f;
    #pragma unroll 4
    for (int n = 0; n < NN; n++) s += p[(size_t)n * NN];
    colsum[idx] = s;
}

// ---------------- 512x512 transpose: Wt[k][d] = W[d][k] ----------------
__global__ void transpose512(const float* __restrict__ in, float* __restrict__ out) {
    __shared__ float tile[32][33];
    int x = blockIdx.x * 32 + threadIdx.x;   // col in 'in'
    int y0 = blockIdx.y * 32 + threadIdx.y;  // row in 'in'
    #pragma unroll
    for (int j = 0; j < 32; j += 8)
        tile[threadIdx.y + j][threadIdx.x] = in[(size_t)(y0 + j) * DD + x];
    __syncthreads();
    int ox = blockIdx.y * 32 + threadIdx.x;
    int oy0 = blockIdx.x * 32 + threadIdx.y;
    #pragma unroll
    for (int j = 0; j < 32; j += 8)
        out[(size_t)(oy0 + j) * DD + ox] = tile[threadIdx.x][threadIdx.y + j];
}

// ---------------- GEMM tiling ----------------
#define BM 128
#define BN 128
#define BK 8
#define TM 8
#define TN 8
// 256 threads per block

// Y[b] = adj[b] @ X[b] + X[b]   (M=N=1024 rows, Ncols=512, K=1024)
__global__ void __launch_bounds__(256)
gemm1_kernel(const float* __restrict__ A, const float* __restrict__ X,
             float* __restrict__ Y) {
    const int bidb = blockIdx.z;
    const int rowBlk = blockIdx.y * BM;
    const int colBlk = blockIdx.x * BN;
    const float* Ab = A + (size_t)bidb * NN * NN;
    const float* Xb = X + (size_t)bidb * NN * DD;
    float* Yb = Y + (size_t)bidb * NN * DD;

    __shared__ float As[BK][BM];
    __shared__ float Bs[BK][BN];

    const int tid = threadIdx.x;
    const int aRow = tid >> 1;            // 0..127
    const int aCol4 = (tid & 1) * 4;      // 0 or 4
    const int bRow = tid >> 5;            // 0..7
    const int bCol4 = (tid & 31) * 4;     // 0..124
    const int ty = tid >> 4;              // 0..15
    const int tx = tid & 15;              // 0..15

    float acc[TM][TN] = {};
    float ar[TM], br[TN];

    for (int k0 = 0; k0 < NN; k0 += BK) {
        float4 av = *reinterpret_cast<const float4*>(
            &Ab[(size_t)(rowBlk + aRow) * NN + k0 + aCol4]);
        As[aCol4 + 0][aRow] = av.x;
        As[aCol4 + 1][aRow] = av.y;
        As[aCol4 + 2][aRow] = av.z;
        As[aCol4 + 3][aRow] = av.w;
        float4 bv = *reinterpret_cast<const float4*>(
            &Xb[(size_t)(k0 + bRow) * DD + colBlk + bCol4]);
        *reinterpret_cast<float4*>(&Bs[bRow][bCol4]) = bv;
        __syncthreads();
        #pragma unroll
        for (int k = 0; k < BK; k++) {
            #pragma unroll
            for (int i = 0; i < TM; i++) ar[i] = As[k][ty * TM + i];
            #pragma unroll
            for (int j = 0; j < TN; j++) br[j] = Bs[k][tx * TN + j];
            #pragma unroll
            for (int i = 0; i < TM; i++)
                #pragma unroll
                for (int j = 0; j < TN; j++)
                    acc[i][j] += ar[i] * br[j];
        }
        __syncthreads();
    }
    // epilogue: Y = acc + X
    #pragma unroll
    for (int i = 0; i < TM; i++) {
        int r = rowBlk + ty * TM + i;
        #pragma unroll
        for (int j = 0; j < TN; j += 4) {
            int c = colBlk + tx * TN + j;
            float4 xv = *reinterpret_cast<const float4*>(&Xb[(size_t)r * DD + c]);
            float4 o;
            o.x = acc[i][j + 0] + xv.x;
            o.y = acc[i][j + 1] + xv.y;
            o.z = acc[i][j + 2] + xv.z;
            o.w = acc[i][j + 3] + xv.w;
            *reinterpret_cast<float4*>(&Yb[(size_t)r * DD + c]) = o;
        }
    }
}

// Xout = relu((Yin @ Wt + 2*Wb) / denom), M = B*N flattened, K = Ncols = 512
__global__ void __launch_bounds__(256)
gemm2_kernel(const float* __restrict__ Yin, const float* __restrict__ Wt,
             const float* __restrict__ Wb, const float* __restrict__ denom,
             float* __restrict__ Xout) {
    const int rowBlk = blockIdx.y * BM;
    const int colBlk = blockIdx.x * BN;

    __shared__ float As[BK][BM];
    __shared__ float Bs[BK][BN];

    const int tid = threadIdx.x;
    const int aRow = tid >> 1;
    const int aCol4 = (tid & 1) * 4;
    const int bRow = tid >> 5;
    const int bCol4 = (tid & 31) * 4;
    const int ty = tid >> 4;
    const int tx = tid & 15;

    float acc[TM][TN] = {};
    float ar[TM], br[TN];

    for (int k0 = 0; k0 < DD; k0 += BK) {
        float4 av = *reinterpret_cast<const float4*>(
            &Yin[(size_t)(rowBlk + aRow) * DD + k0 + aCol4]);
        As[aCol4 + 0][aRow] = av.x;
        As[aCol4 + 1][aRow] = av.y;
        As[aCol4 + 2][aRow] = av.z;
        As[aCol4 + 3][aRow] = av.w;
        float4 bv = *reinterpret_cast<const float4*>(
            &Wt[(size_t)(k0 + bRow) * DD + colBlk + bCol4]);
        *reinterpret_cast<float4*>(&Bs[bRow][bCol4]) = bv;
        __syncthreads();
        #pragma unroll
        for (int k = 0; k < BK; k++) {
            #pragma unroll
            for (int i = 0; i < TM; i++) ar[i] = As[k][ty * TM + i];
            #pragma unroll
            for (int j = 0; j < TN; j++) br[j] = Bs[k][tx * TN + j];
            #pragma unroll
            for (int i = 0; i < TM; i++)
                #pragma unroll
                for (int j = 0; j < TN; j++)
                    acc[i][j] += ar[i] * br[j];
        }
        __syncthreads();
    }
    #pragma unroll
    for (int i = 0; i < TM; i++) {
        int r = rowBlk + ty * TM + i;
        float inv = 1.0f / denom[r];
        #pragma unroll
        for (int j = 0; j < TN; j += 4) {
            int c = colBlk + tx * TN + j;
            float4 o;
            o.x = fmaxf((acc[i][j + 0] + 2.0f * Wb[c + 0]) * inv, 0.0f);
            o.y = fmaxf((acc[i][j + 1] + 2.0f * Wb[c + 1]) * inv, 0.0f);
            o.z = fmaxf((acc[i][j + 2] + 2.0f * Wb[c + 2]) * inv, 0.0f);
            o.w = fmaxf((acc[i][j + 3] + 2.0f * Wb[c + 3]) * inv, 0.0f);
            *reinterpret_cast<float4*>(&Xout[(size_t)r * DD + c]) = o;
        }
    }
}

// ---------------- LayerNorm (two-pass, matches reference) ----------------
__global__ void ln_kernel(const float* __restrict__ X, const float* __restrict__ g,
                          const float* __restrict__ b, float* __restrict__ out) {
    __shared__ float sh[32];
    const int row = blockIdx.x;
    const float* p = X + (size_t)row * DD;
    const int tid = threadIdx.x;              // 256 threads, 2 elems each
    float v0 = p[tid];
    float v1 = p[tid + 256];
    float mu = block_reduce_sum(v0 + v1, sh) * (1.0f / DD);
    float d0 = v0 - mu, d1 = v1 - mu;
    float var = block_reduce_sum(d0 * d0 + d1 * d1, sh) * (1.0f / DD);
    float r = rsqrtf(var + LN_EPS);
    out[(size_t)row * DD + tid] = d0 * r * g[tid] + b[tid];
    out[(size_t)row * DD + tid + 256] = d1 * r * g[tid + 256] + b[tid + 256];
}

// ---------------- masks ----------------
__global__ void mask_kernel(const float* __restrict__ denom,
                            const float* __restrict__ colsum,
                            float* __restrict__ out, int count) {
    int i = blockIdx.x * blockDim.x + threadIdx.x;
    if (i >= count) return;
    if (i < BB * NN) {
        float rs = denom[i] - 1.0f;
        out[i] = ((rs + colsum[i]) == 0.0f) ? 1.0f : 0.0f;
    } else {
        out[i] = 0.0f;
    }
}

// ---------------- launch ----------------
extern "C" void kernel_launch(void* const* d_in, const int* in_sizes, int n_in,
                              void* d_out, int out_size) {
    const float* adj = (const float*)d_in[0];
    const float* emb = (const float*)d_in[1];
    // d_in[2] = seq_lens (all N, unused)
    const float* W0w = (const float*)d_in[3];
    const float* W0b = (const float*)d_in[4];
    const float* W1w = (const float*)d_in[5];
    const float* W1b = (const float*)d_in[6];
    const float* lng = (const float*)d_in[7];
    const float* lnb = (const float*)d_in[8];
    float* out = (float*)d_out;

    float *denom, *colsum, *y, *x, *wt0, *wt1;
    cudaGetSymbolAddress((void**)&denom, g_denom);
    cudaGetSymbolAddress((void**)&colsum, g_colsum);
    cudaGetSymbolAddress((void**)&y, g_y);
    cudaGetSymbolAddress((void**)&x, g_x);
    cudaGetSymbolAddress((void**)&wt0, g_Wt0);
    cudaGetSymbolAddress((void**)&wt1, g_Wt1);

    rowsum_kernel<<<BB * NN, 256>>>(adj, denom);
    colsum_kernel<<<(BB * NN + 255) / 256, 256>>>(adj, colsum);

    dim3 tb(32, 8);
    transpose512<<<dim3(DD / 32, DD / 32), tb>>>(W0w, wt0);
    transpose512<<<dim3(DD / 32, DD / 32), tb>>>(W1w, wt1);

    dim3 g1(DD / BN, NN / BM, BB);           // (4, 8, 32)
    dim3 g2(DD / BN, (BB * NN) / BM);        // (4, 256)

    // layer 0
    gemm1_kernel<<<g1, 256>>>(adj, emb, y);
    gemm2_kernel<<<g2, 256>>>(y, wt0, W0b, denom, x);
    // layer 1
    gemm1_kernel<<<g1, 256>>>(adj, x, y);
    gemm2_kernel<<<g2, 256>>>(y, wt1, W1b, denom, x);

    ln_kernel<<<BB * NN, 256>>>(x, lng, lnb, out);

    int extra = out_size - BB * NN * DD;
    if (extra > 0) {
        mask_kernel<<<(extra + 255) / 256, 256>>>(denom, colsum,
                                                  out + (size_t)BB * NN * DD, extra);
    }
}

// round 3
// speedup vs baseline: 2.1772x; 2.1772x over previous
#include <cuda_runtime.h>
#include <cuda_fp16.h>
#include <cstdint>

#define BB 32
#define NN 1024
#define DD 512
#define LN_EPS 1e-5f

// ---------------- scratch (no allocations allowed) ----------------
__device__ float  g_denom[BB * NN];
__device__ float  g_colsum[BB * NN];
__device__ float  g_x[BB * NN * DD];                 // fp32 layer activations
__device__ __half g_adj_h[(size_t)BB * NN * NN];     // adj split
__device__ __half g_adj_l[(size_t)BB * NN * NN];
__device__ __half g_xT_h[(size_t)BB * DD * NN];      // X^T split (B operand of gemm1)
__device__ __half g_xT_l[(size_t)BB * DD * NN];
__device__ __half g_y_h[(size_t)BB * NN * DD];       // gemm1 output split (A of gemm2)
__device__ __half g_y_l[(size_t)BB * NN * DD];
__device__ __half g_W0_h[DD * DD];
__device__ __half g_W0_l[DD * DD];
__device__ __half g_W1_h[DD * DD];
__device__ __half g_W1_l[DD * DD];

// ---------------- PTX helpers (base sm_103-safe: cp.async / ldmatrix / mma.sync) ----
__device__ __forceinline__ uint32_t smem_u32(const void* p) {
    uint32_t a;
    asm("{ .reg .u64 t; cvta.to.shared.u64 t, %1; cvt.u32.u64 %0, t; }" : "=r"(a) : "l"(p));
    return a;
}
__device__ __forceinline__ void cp_async16(uint32_t dst, const void* src) {
    asm volatile("cp.async.cg.shared.global [%0], [%1], 16;" :: "r"(dst), "l"(src));
}
__device__ __forceinline__ void cp_commit() { asm volatile("cp.async.commit_group;" ::: "memory"); }
template <int N>
__device__ __forceinline__ void cp_wait() { asm volatile("cp.async.wait_group %0;" :: "n"(N) : "memory"); }

__device__ __forceinline__ void ldsm4(uint32_t* r, uint32_t addr) {
    asm volatile("ldmatrix.sync.aligned.m8n8.x4.shared.b16 {%0,%1,%2,%3}, [%4];"
                 : "=r"(r[0]), "=r"(r[1]), "=r"(r[2]), "=r"(r[3]) : "r"(addr));
}
__device__ __forceinline__ void mma16816(float* c, const uint32_t* a, const uint32_t* b) {
    asm volatile("mma.sync.aligned.m16n8k16.row.col.f32.f16.f16.f32 "
                 "{%0,%1,%2,%3}, {%4,%5,%6,%7}, {%8,%9}, {%0,%1,%2,%3};"
                 : "+f"(c[0]), "+f"(c[1]), "+f"(c[2]), "+f"(c[3])
                 : "r"(a[0]), "r"(a[1]), "r"(a[2]), "r"(a[3]), "r"(b[0]), "r"(b[1]));
}

// ---------------- small kernels ----------------
__device__ __forceinline__ float block_reduce_sum(float v, float* sh) {
    __syncthreads();
    int tid = threadIdx.x;
    #pragma unroll
    for (int o = 16; o > 0; o >>= 1) v += __shfl_down_sync(0xffffffff, v, o);
    if ((tid & 31) == 0) sh[tid >> 5] = v;
    __syncthreads();
    if (tid < 32) {
        v = (tid < (int)(blockDim.x >> 5)) ? sh[tid] : 0.0f;
        #pragma unroll
        for (int o = 16; o > 0; o >>= 1) v += __shfl_down_sync(0xffffffff, v, o);
        if (tid == 0) sh[0] = v;
    }
    __syncthreads();
    return sh[0];
}

__global__ void rowsum_kernel(const float* __restrict__ adj, float* __restrict__ denom) {
    __shared__ float sh[32];
    const int row = blockIdx.x;
    const float* p = adj + (size_t)row * NN;
    float s = 0.0f;
    for (int i = threadIdx.x; i < NN; i += blockDim.x) s += p[i];
    float tot = block_reduce_sum(s, sh);
    if (threadIdx.x == 0) denom[row] = tot + 1.0f;
}

__global__ void colsum_kernel(const float* __restrict__ adj, float* __restrict__ colsum) {
    int idx = blockIdx.x * blockDim.x + threadIdx.x;
    if (idx >= BB * NN) return;
    int b = idx / NN, m = idx % NN;
    const float* p = adj + (size_t)b * NN * NN + m;
    float s = 0.0f;
    #pragma unroll 4
    for (int n = 0; n < NN; n++) s += p[(size_t)n * NN];
    colsum[idx] = s;
}

__global__ void split_kernel(const float* __restrict__ src, __half* __restrict__ h,
                             __half* __restrict__ l, int n4) {
    int i = blockIdx.x * blockDim.x + threadIdx.x;
    if (i >= n4) return;
    float4 v = reinterpret_cast<const float4*>(src)[i];
    __half h0 = __float2half_rn(v.x), h1 = __float2half_rn(v.y);
    __half h2 = __float2half_rn(v.z), h3 = __float2half_rn(v.w);
    __half l0 = __float2half_rn(v.x - __half2float(h0));
    __half l1 = __float2half_rn(v.y - __half2float(h1));
    __half l2 = __float2half_rn(v.z - __half2float(h2));
    __half l3 = __float2half_rn(v.w - __half2float(h3));
    reinterpret_cast<__half2*>(h)[i * 2 + 0] = __halves2half2(h0, h1);
    reinterpret_cast<__half2*>(h)[i * 2 + 1] = __halves2half2(h2, h3);
    reinterpret_cast<__half2*>(l)[i * 2 + 0] = __halves2half2(l0, l1);
    reinterpret_cast<__half2*>(l)[i * 2 + 1] = __halves2half2(l2, l3);
}

__global__ void transpose_split(const float* __restrict__ x, __half* __restrict__ th,
                                __half* __restrict__ tl) {
    __shared__ float tile[32][33];
    int b = blockIdx.z;
    int m0 = blockIdx.y * 32, d0 = blockIdx.x * 32;
    const float* src = x + (size_t)b * NN * DD;
    int tx = threadIdx.x, ty = threadIdx.y;
    #pragma unroll
    for (int j = 0; j < 32; j += 8)
        tile[ty + j][tx] = src[(size_t)(m0 + ty + j) * DD + d0 + tx];
    __syncthreads();
    __half* dh = th + (size_t)b * DD * NN;
    __half* dl = tl + (size_t)b * DD * NN;
    #pragma unroll
    for (int j = 0; j < 32; j += 8) {
        float v = tile[tx][ty + j];
        __half h = __float2half_rn(v);
        __half l = __float2half_rn(v - __half2float(h));
        dh[(size_t)(d0 + ty + j) * NN + m0 + tx] = h;
        dl[(size_t)(d0 + ty + j) * NN + m0 + tx] = l;
    }
}

// ---------------- HMMA GEMM: 128x128 block tile, K-chunks of 64 ----------------
// D = Ah@Bh^T + Ah@Bl^T + Al@Bh^T (B stored K-major: B[n][k]), fp32 acc in regs.
// EPI=1: out = D + X -> fp16 hi/lo split (OutH, OutL)   [gemm1: Y = adj@X + X]
// EPI=2: out = relu((D + 2*bias)/denom) -> OutF fp32     [gemm2]
#define KT 64
#define TBYTES 16384          // one 128x64 fp16 tile
#define STAGE_BYTES (4 * TBYTES)

template <int KTOT, int EPI>
__global__ void __launch_bounds__(256, 1)
gemm_hmma(const __half* __restrict__ Ah, const __half* __restrict__ Al,
          const __half* __restrict__ Bh, const __half* __restrict__ Bl,
          const float* __restrict__ Xadd, __half* __restrict__ OutH, __half* __restrict__ OutL,
          const float* __restrict__ bias, const float* __restrict__ denom,
          float* __restrict__ OutF) {
    extern __shared__ char smem[];
    const uint32_t sb = smem_u32(smem);
    const int tid = threadIdx.x;
    const int wid = tid >> 5;
    const int lane = tid & 31;

    long aRow0, bRow0, outRow0;
    if (EPI == 1) {
        int b = blockIdx.z;
        aRow0 = (long)b * NN + blockIdx.y * 128;
        bRow0 = (long)b * DD + blockIdx.x * 128;
        outRow0 = aRow0;
    } else {
        aRow0 = (long)blockIdx.y * 128;
        bRow0 = (long)blockIdx.x * 128;
        outRow0 = aRow0;
    }
    const int colBlk = blockIdx.x * 128;

    const __half* srcA_h = Ah + aRow0 * KTOT;
    const __half* srcA_l = Al + aRow0 * KTOT;
    const __half* srcB_h = Bh + bRow0 * KTOT;
    const __half* srcB_l = Bl + bRow0 * KTOT;

    const int m0 = (wid >> 2) * 64;   // warp M offset (0 / 64)
    const int n0 = (wid & 3) * 32;    // warp N offset (0..96)

    // ldmatrix lane geometry (x4: 4 tiles of 8 rows x 16B)
    const int ltile = lane >> 3;
    const int rowInTile = (lane & 7) + ((ltile & 1) << 3);  // 0..15
    const int kk = ltile >> 1;                               // 0 or 1 (k8 halves)
    const int lx = lane & 7;                                 // swizzle key

    float acc[4][4][4];
    #pragma unroll
    for (int a = 0; a < 4; a++)
        #pragma unroll
        for (int b2 = 0; b2 < 4; b2++)
            #pragma unroll
            for (int c = 0; c < 4; c++) acc[a][b2][c] = 0.0f;

    const int nk = KTOT / KT;

    // ---- cp.async fill of one stage ----
    auto issue = [&](int i) {
        const uint32_t stg = sb + (uint32_t)(i & 1) * STAGE_BYTES;
        const int k0 = i * KT;
        #pragma unroll
        for (int t = 0; t < 4; t++) {
            const __half* base = (t == 0) ? srcA_h : (t == 1) ? srcA_l
                               : (t == 2) ? srcB_h : srcB_l;
            #pragma unroll
            for (int jj = 0; jj < 4; jj++) {
                int cid = tid + jj * 256;          // 0..1023
                int row = cid >> 3, c = cid & 7;   // row 0..127, 16B chunk 0..7
                cp_async16(stg + t * TBYTES + row * 128 + ((c ^ (row & 7)) << 4),
                           base + (size_t)row * KTOT + k0 + c * 8);
            }
        }
        cp_commit();
    };

    issue(0);

    for (int i = 0; i < nk; i++) {
        if (i + 1 < nk) issue(i + 1);
        if (i + 1 < nk) cp_wait<1>(); else cp_wait<0>();
        __syncthreads();

        const uint32_t stg = sb + (uint32_t)(i & 1) * STAGE_BYTES;
        const uint32_t sAh = stg, sAl = stg + TBYTES, sBh = stg + 2 * TBYTES, sBl = stg + 3 * TBYTES;

        #pragma unroll
        for (int ks = 0; ks < 4; ks++) {
            const uint32_t swz = (uint32_t)(((ks * 2 + kk) ^ lx) << 4);
            uint32_t ah[4][4], al[4][4], bh[4][2], bl[4][2];
            #pragma unroll
            for (int mf = 0; mf < 4; mf++) {
                uint32_t off = (uint32_t)((m0 + mf * 16 + rowInTile) * 128) + swz;
                ldsm4(ah[mf], sAh + off);
                ldsm4(al[mf], sAl + off);
            }
            #pragma unroll
            for (int nh = 0; nh < 2; nh++) {
                uint32_t off = (uint32_t)((n0 + nh * 16 + rowInTile) * 128) + swz;
                uint32_t r[4], s[4];
                ldsm4(r, sBh + off);
                ldsm4(s, sBl + off);
                bh[nh * 2][0] = r[0]; bh[nh * 2][1] = r[2];
                bh[nh * 2 + 1][0] = r[1]; bh[nh * 2 + 1][1] = r[3];
                bl[nh * 2][0] = s[0]; bl[nh * 2][1] = s[2];
                bl[nh * 2 + 1][0] = s[1]; bl[nh * 2 + 1][1] = s[3];
            }
            #pragma unroll
            for (int mf = 0; mf < 4; mf++)
                #pragma unroll
                for (int nf = 0; nf < 4; nf++) {
                    mma16816(acc[mf][nf], ah[mf], bh[nf]);
                    mma16816(acc[mf][nf], ah[mf], bl[nf]);
                    mma16816(acc[mf][nf], al[mf], bh[nf]);
                }
        }
        __syncthreads();
    }

    // ---- epilogue: direct to GMEM (float2 / half2 granularity) ----
    const int rr = lane >> 2;           // 0..7
    const int cc = (lane & 3) * 2;      // 0,2,4,6
    #pragma unroll
    for (int mf = 0; mf < 4; mf++) {
        #pragma unroll
        for (int half = 0; half < 2; half++) {
            long grow = outRow0 + m0 + mf * 16 + rr + half * 8;
            float invd = (EPI == 2) ? (1.0f / denom[grow]) : 0.0f;
            #pragma unroll
            for (int nf = 0; nf < 4; nf++) {
                int gcol = colBlk + n0 + nf * 8 + cc;
                size_t gi = (size_t)grow * DD + gcol;
                float v0 = acc[mf][nf][half * 2 + 0];
                float v1 = acc[mf][nf][half * 2 + 1];
                if (EPI == 1) {
                    float2 xv = *reinterpret_cast<const float2*>(&Xadd[gi]);
                    v0 += xv.x; v1 += xv.y;
                    __half h0 = __float2half_rn(v0), h1 = __float2half_rn(v1);
                    __half l0 = __float2half_rn(v0 - __half2float(h0));
                    __half l1 = __float2half_rn(v1 - __half2float(h1));
                    *reinterpret_cast<__half2*>(&OutH[gi]) = __halves2half2(h0, h1);
                    *reinterpret_cast<__half2*>(&OutL[gi]) = __halves2half2(l0, l1);
                } else {
                    float2 bv = *reinterpret_cast<const float2*>(&bias[gcol]);
                    float2 o;
                    o.x = fmaxf((v0 + 2.0f * bv.x) * invd, 0.0f);
                    o.y = fmaxf((v1 + 2.0f * bv.y) * invd, 0.0f);
                    *reinterpret_cast<float2*>(&OutF[gi]) = o;
                }
            }
        }
    }
}

// ---------------- LayerNorm ----------------
__global__ void ln_kernel(const float* __restrict__ X, const float* __restrict__ g,
                          const float* __restrict__ b, float* __restrict__ out) {
    __shared__ float sh[32];
    const int row = blockIdx.x;
    const float* p = X + (size_t)row * DD;
    const int tid = threadIdx.x;
    float v0 = p[tid];
    float v1 = p[tid + 256];
    float mu = block_reduce_sum(v0 + v1, sh) * (1.0f / DD);
    float d0 = v0 - mu, d1 = v1 - mu;
    float var = block_reduce_sum(d0 * d0 + d1 * d1, sh) * (1.0f / DD);
    float r = rsqrtf(var + LN_EPS);
    out[(size_t)row * DD + tid] = d0 * r * g[tid] + b[tid];
    out[(size_t)row * DD + tid + 256] = d1 * r * g[tid + 256] + b[tid + 256];
}

__global__ void mask_kernel(const float* __restrict__ denom, const float* __restrict__ colsum,
                            float* __restrict__ out, int count) {
    int i = blockIdx.x * blockDim.x + threadIdx.x;
    if (i >= count) return;
    if (i < BB * NN) {
        float rs = denom[i] - 1.0f;
        out[i] = ((rs + colsum[i]) == 0.0f) ? 1.0f : 0.0f;
    } else {
        out[i] = 0.0f;
    }
}

// ---------------- launch ----------------
#define GEMM_SMEM (2 * STAGE_BYTES)

extern "C" void kernel_launch(void* const* d_in, const int* in_sizes, int n_in,
                              void* d_out, int out_size) {
    const float* adj = (const float*)d_in[0];
    const float* emb = (const float*)d_in[1];
    const float* W0w = (const float*)d_in[3];
    const float* W0b = (const float*)d_in[4];
    const float* W1w = (const float*)d_in[5];
    const float* W1b = (const float*)d_in[6];
    const float* lng = (const float*)d_in[7];
    const float* lnb = (const float*)d_in[8];
    float* out = (float*)d_out;

    float *denom, *colsum, *x;
    __half *adjh, *adjl, *xth, *xtl, *yh, *yl, *w0h, *w0l, *w1h, *w1l;
    cudaGetSymbolAddress((void**)&denom, g_denom);
    cudaGetSymbolAddress((void**)&colsum, g_colsum);
    cudaGetSymbolAddress((void**)&x, g_x);
    cudaGetSymbolAddress((void**)&adjh, g_adj_h);
    cudaGetSymbolAddress((void**)&adjl, g_adj_l);
    cudaGetSymbolAddress((void**)&xth, g_xT_h);
    cudaGetSymbolAddress((void**)&xtl, g_xT_l);
    cudaGetSymbolAddress((void**)&yh, g_y_h);
    cudaGetSymbolAddress((void**)&yl, g_y_l);
    cudaGetSymbolAddress((void**)&w0h, g_W0_h);
    cudaGetSymbolAddress((void**)&w0l, g_W0_l);
    cudaGetSymbolAddress((void**)&w1h, g_W1_h);
    cudaGetSymbolAddress((void**)&w1l, g_W1_l);

    cudaFuncSetAttribute(gemm_hmma<1024, 1>, cudaFuncAttributeMaxDynamicSharedMemorySize, GEMM_SMEM);
    cudaFuncSetAttribute(gemm_hmma<512, 2>, cudaFuncAttributeMaxDynamicSharedMemorySize, GEMM_SMEM);

    rowsum_kernel<<<BB * NN, 256>>>(adj, denom);
    colsum_kernel<<<(BB * NN + 255) / 256, 256>>>(adj, colsum);

    {
        int n4 = (BB * NN * NN) / 4;
        split_kernel<<<(n4 + 255) / 256, 256>>>(adj, adjh, adjl, n4);
        int w4 = (DD * DD) / 4;
        split_kernel<<<(w4 + 255) / 256, 256>>>(W0w, w0h, w0l, w4);
        split_kernel<<<(w4 + 255) / 256, 256>>>(W1w, w1h, w1l, w4);
    }

    dim3 tg(DD / 32, NN / 32, BB);
    dim3 tb(32, 8);
    dim3 g1(DD / 128, NN / 128, BB);         // (4, 8, 32)
    dim3 g2(DD / 128, (BB * NN) / 128, 1);   // (4, 256)

    // layer 0
    transpose_split<<<tg, tb>>>(emb, xth, xtl);
    gemm_hmma<1024, 1><<<g1, 256, GEMM_SMEM>>>(adjh, adjl, xth, xtl, emb, yh, yl,
                                               nullptr, nullptr, nullptr);
    gemm_hmma<512, 2><<<g2, 256, GEMM_SMEM>>>(yh, yl, w0h, w0l, nullptr, nullptr, nullptr,
                                              W0b, denom, x);
    // layer 1
    transpose_split<<<tg, tb>>>(x, xth, xtl);
    gemm_hmma<1024, 1><<<g1, 256, GEMM_SMEM>>>(adjh, adjl, xth, xtl, x, yh, yl,
                                               nullptr, nullptr, nullptr);
    gemm_hmma<512, 2><<<g2, 256, GEMM_SMEM>>>(yh, yl, w1h, w1l, nullptr, nullptr, nullptr,
                                              W1b, denom, x);

    ln_kernel<<<BB * NN, 256>>>(x, lng, lnb, out);

    int extra = out_size - BB * NN * DD;
    if (extra > 0) {
        mask_kernel<<<(extra + 255) / 256, 256>>>(denom, colsum,
                                                  out + (size_t)BB * NN * DD, extra);
    }
}

// round 4
// speedup vs baseline: 2.4054x; 1.1048x over previous
#include <cuda_runtime.h>
#include <cuda_fp16.h>
#include <cstdint>

#define BB 32
#define NN 1024
#define DD 512
#define LN_EPS 1e-5f

// ---------------- scratch (no allocations allowed) ----------------
__device__ float  g_denom[BB * NN];
__device__ float  g_colsum[BB * NN];
__device__ float  g_x[BB * NN * DD];                 // fp32 layer activations
__device__ __half g_adj_h[(size_t)BB * NN * NN];     // adj split
__device__ __half g_adj_l[(size_t)BB * NN * NN];
__device__ __half g_xT_h[(size_t)BB * DD * NN];      // X^T split (B operand of gemm1)
__device__ __half g_xT_l[(size_t)BB * DD * NN];
__device__ __half g_y_h[(size_t)BB * NN * DD];       // gemm1 output split (A of gemm2)
__device__ __half g_y_l[(size_t)BB * NN * DD];
__device__ __half g_W0_h[DD * DD];
__device__ __half g_W0_l[DD * DD];
__device__ __half g_W1_h[DD * DD];
__device__ __half g_W1_l[DD * DD];

// ---------------- PTX helpers (base sm_103-safe) ----------------
__device__ __forceinline__ uint32_t smem_u32(const void* p) {
    uint32_t a;
    asm("{ .reg .u64 t; cvta.to.shared.u64 t, %1; cvt.u32.u64 %0, t; }" : "=r"(a) : "l"(p));
    return a;
}
__device__ __forceinline__ void cp_async16(uint32_t dst, const void* src) {
    asm volatile("cp.async.cg.shared.global [%0], [%1], 16;" :: "r"(dst), "l"(src));
}
__device__ __forceinline__ void cp_commit() { asm volatile("cp.async.commit_group;" ::: "memory"); }
template <int N>
__device__ __forceinline__ void cp_wait() { asm volatile("cp.async.wait_group %0;" :: "n"(N) : "memory"); }

__device__ __forceinline__ void ldsm4(uint32_t* r, uint32_t addr) {
    asm volatile("ldmatrix.sync.aligned.m8n8.x4.shared.b16 {%0,%1,%2,%3}, [%4];"
                 : "=r"(r[0]), "=r"(r[1]), "=r"(r[2]), "=r"(r[3]) : "r"(addr));
}
__device__ __forceinline__ void mma16816(float* c, const uint32_t* a, const uint32_t* b) {
    asm volatile("mma.sync.aligned.m16n8k16.row.col.f32.f16.f16.f32 "
                 "{%0,%1,%2,%3}, {%4,%5,%6,%7}, {%8,%9}, {%0,%1,%2,%3};"
                 : "+f"(c[0]), "+f"(c[1]), "+f"(c[2]), "+f"(c[3])
                 : "r"(a[0]), "r"(a[1]), "r"(a[2]), "r"(a[3]), "r"(b[0]), "r"(b[1]));
}

// ---------------- reductions ----------------
__device__ __forceinline__ float block_reduce_sum(float v, float* sh) {
    __syncthreads();
    int tid = threadIdx.x;
    #pragma unroll
    for (int o = 16; o > 0; o >>= 1) v += __shfl_down_sync(0xffffffff, v, o);
    if ((tid & 31) == 0) sh[tid >> 5] = v;
    __syncthreads();
    if (tid < 32) {
        v = (tid < (int)(blockDim.x >> 5)) ? sh[tid] : 0.0f;
        #pragma unroll
        for (int o = 16; o > 0; o >>= 1) v += __shfl_down_sync(0xffffffff, v, o);
        if (tid == 0) sh[0] = v;
    }
    __syncthreads();
    return sh[0];
}

// ---------------- fused adj pass: rowsum+1 -> denom, colsum (atomic), fp16 split ----
// grid (8, BB), block 256. Each block: 128 rows x 1024 cols of one batch.
__global__ void __launch_bounds__(256)
adj_pass_kernel(const float* __restrict__ adj, float* __restrict__ denom,
                float* __restrict__ colsum, __half* __restrict__ Ah,
                __half* __restrict__ Al) {
    __shared__ float rowacc[128];
    const int b = blockIdx.y;
    const int r0 = blockIdx.x * 128;
    const int tid = threadIdx.x;
    const int lane = tid & 31;
    const int col0 = tid * 4;

    for (int i = tid; i < 128; i += 256) rowacc[i] = 0.0f;
    __syncthreads();

    const float* src = adj + (size_t)b * NN * NN + (size_t)r0 * NN;
    __half* dh = Ah + (size_t)b * NN * NN + (size_t)r0 * NN;
    __half* dl = Al + (size_t)b * NN * NN + (size_t)r0 * NN;

    float cs0 = 0.f, cs1 = 0.f, cs2 = 0.f, cs3 = 0.f;

    for (int r = 0; r < 128; r++) {
        float4 v = *reinterpret_cast<const float4*>(&src[(size_t)r * NN + col0]);
        // split
        __half h0 = __float2half_rn(v.x), h1 = __float2half_rn(v.y);
        __half h2 = __float2half_rn(v.z), h3 = __float2half_rn(v.w);
        __half l0 = __float2half_rn(v.x - __half2float(h0));
        __half l1 = __float2half_rn(v.y - __half2float(h1));
        __half l2 = __float2half_rn(v.z - __half2float(h2));
        __half l3 = __float2half_rn(v.w - __half2float(h3));
        *reinterpret_cast<__half2*>(&dh[(size_t)r * NN + col0])     = __halves2half2(h0, h1);
        *reinterpret_cast<__half2*>(&dh[(size_t)r * NN + col0 + 2]) = __halves2half2(h2, h3);
        *reinterpret_cast<__half2*>(&dl[(size_t)r * NN + col0])     = __halves2half2(l0, l1);
        *reinterpret_cast<__half2*>(&dl[(size_t)r * NN + col0 + 2]) = __halves2half2(l2, l3);
        // col partials (registers)
        cs0 += v.x; cs1 += v.y; cs2 += v.z; cs3 += v.w;
        // row sum: warp reduce, lane0 atomically adds to smem
        float s = (v.x + v.y) + (v.z + v.w);
        #pragma unroll
        for (int o = 16; o > 0; o >>= 1) s += __shfl_down_sync(0xffffffff, s, o);
        if (lane == 0) atomicAdd(&rowacc[r], s);
    }
    __syncthreads();
    if (tid < 128) denom[(size_t)b * NN + r0 + tid] = rowacc[tid] + 1.0f;
    // col sums -> global atomics (8 adds per column total)
    float* cdst = colsum + (size_t)b * NN + col0;
    atomicAdd(cdst + 0, cs0);
    atomicAdd(cdst + 1, cs1);
    atomicAdd(cdst + 2, cs2);
    atomicAdd(cdst + 3, cs3);
}

__global__ void zero_kernel(float* __restrict__ p, int n) {
    int i = blockIdx.x * blockDim.x + threadIdx.x;
    if (i < n) p[i] = 0.0f;
}

__global__ void split_kernel(const float* __restrict__ src, __half* __restrict__ h,
                             __half* __restrict__ l, int n4) {
    int i = blockIdx.x * blockDim.x + threadIdx.x;
    if (i >= n4) return;
    float4 v = reinterpret_cast<const float4*>(src)[i];
    __half h0 = __float2half_rn(v.x), h1 = __float2half_rn(v.y);
    __half h2 = __float2half_rn(v.z), h3 = __float2half_rn(v.w);
    __half l0 = __float2half_rn(v.x - __half2float(h0));
    __half l1 = __float2half_rn(v.y - __half2float(h1));
    __half l2 = __float2half_rn(v.z - __half2float(h2));
    __half l3 = __float2half_rn(v.w - __half2float(h3));
    reinterpret_cast<__half2*>(h)[i * 2 + 0] = __halves2half2(h0, h1);
    reinterpret_cast<__half2*>(h)[i * 2 + 1] = __halves2half2(h2, h3);
    reinterpret_cast<__half2*>(l)[i * 2 + 0] = __halves2half2(l0, l1);
    reinterpret_cast<__half2*>(l)[i * 2 + 1] = __halves2half2(l2, l3);
}

__global__ void transpose_split(const float* __restrict__ x, __half* __restrict__ th,
                                __half* __restrict__ tl) {
    __shared__ float tile[32][33];
    int b = blockIdx.z;
    int m0 = blockIdx.y * 32, d0 = blockIdx.x * 32;
    const float* src = x + (size_t)b * NN * DD;
    int tx = threadIdx.x, ty = threadIdx.y;
    #pragma unroll
    for (int j = 0; j < 32; j += 8)
        tile[ty + j][tx] = src[(size_t)(m0 + ty + j) * DD + d0 + tx];
    __syncthreads();
    __half* dh = th + (size_t)b * DD * NN;
    __half* dl = tl + (size_t)b * DD * NN;
    #pragma unroll
    for (int j = 0; j < 32; j += 8) {
        float v = tile[tx][ty + j];
        __half h = __float2half_rn(v);
        __half l = __float2half_rn(v - __half2float(h));
        dh[(size_t)(d0 + ty + j) * NN + m0 + tx] = h;
        dl[(size_t)(d0 + ty + j) * NN + m0 + tx] = l;
    }
}

// ---------------- HMMA GEMM: 128x128 block tile, K-chunks of 64 ----------------
// D = Ah@Bh^T + Ah@Bl^T + Al@Bh^T (B stored K-major), fp32 acc in regs.
// MMA issue order: three term-passes over all 16 acc tiles -> no acc RAW chains.
#define KT 64
#define TBYTES 16384
#define STAGE_BYTES (4 * TBYTES)

template <int KTOT, int EPI>
__global__ void __launch_bounds__(256, 1)
gemm_hmma(const __half* __restrict__ Ah, const __half* __restrict__ Al,
          const __half* __restrict__ Bh, const __half* __restrict__ Bl,
          const float* __restrict__ Xadd, __half* __restrict__ OutH, __half* __restrict__ OutL,
          const float* __restrict__ bias, const float* __restrict__ denom,
          float* __restrict__ OutF) {
    extern __shared__ char smem[];
    const uint32_t sb = smem_u32(smem);
    const int tid = threadIdx.x;
    const int wid = tid >> 5;
    const int lane = tid & 31;

    long aRow0, bRow0, outRow0;
    if (EPI == 1) {
        int b = blockIdx.z;
        aRow0 = (long)b * NN + blockIdx.y * 128;
        bRow0 = (long)b * DD + blockIdx.x * 128;
        outRow0 = aRow0;
    } else {
        aRow0 = (long)blockIdx.y * 128;
        bRow0 = (long)blockIdx.x * 128;
        outRow0 = aRow0;
    }
    const int colBlk = blockIdx.x * 128;

    const __half* srcA_h = Ah + aRow0 * KTOT;
    const __half* srcA_l = Al + aRow0 * KTOT;
    const __half* srcB_h = Bh + bRow0 * KTOT;
    const __half* srcB_l = Bl + bRow0 * KTOT;

    const int m0 = (wid >> 2) * 64;
    const int n0 = (wid & 3) * 32;

    const int ltile = lane >> 3;
    const int rowInTile = (lane & 7) + ((ltile & 1) << 3);
    const int kk = ltile >> 1;
    const int lx = lane & 7;

    float acc[4][4][4];
    #pragma unroll
    for (int a = 0; a < 4; a++)
        #pragma unroll
        for (int b2 = 0; b2 < 4; b2++)
            #pragma unroll
            for (int c = 0; c < 4; c++) acc[a][b2][c] = 0.0f;

    const int nk = KTOT / KT;

    auto issue = [&](int i) {
        const uint32_t stg = sb + (uint32_t)(i & 1) * STAGE_BYTES;
        const int k0 = i * KT;
        #pragma unroll
        for (int t = 0; t < 4; t++) {
            const __half* base = (t == 0) ? srcA_h : (t == 1) ? srcA_l
                               : (t == 2) ? srcB_h : srcB_l;
            #pragma unroll
            for (int jj = 0; jj < 4; jj++) {
                int cid = tid + jj * 256;
                int row = cid >> 3, c = cid & 7;
                cp_async16(stg + t * TBYTES + row * 128 + ((c ^ (row & 7)) << 4),
                           base + (size_t)row * KTOT + k0 + c * 8);
            }
        }
        cp_commit();
    };

    issue(0);

    for (int i = 0; i < nk; i++) {
        if (i + 1 < nk) issue(i + 1);
        if (i + 1 < nk) cp_wait<1>(); else cp_wait<0>();
        __syncthreads();

        const uint32_t stg = sb + (uint32_t)(i & 1) * STAGE_BYTES;
        const uint32_t sAh = stg, sAl = stg + TBYTES, sBh = stg + 2 * TBYTES, sBl = stg + 3 * TBYTES;

        #pragma unroll
        for (int ks = 0; ks < 4; ks++) {
            const uint32_t swz = (uint32_t)(((ks * 2 + kk) ^ lx) << 4);
            uint32_t ah[4][4], al[4][4], bh[4][2], bl[4][2];
            #pragma unroll
            for (int mf = 0; mf < 4; mf++) {
                uint32_t off = (uint32_t)((m0 + mf * 16 + rowInTile) * 128) + swz;
                ldsm4(ah[mf], sAh + off);
                ldsm4(al[mf], sAl + off);
            }
            #pragma unroll
            for (int nh = 0; nh < 2; nh++) {
                uint32_t off = (uint32_t)((n0 + nh * 16 + rowInTile) * 128) + swz;
                uint32_t r[4], s[4];
                ldsm4(r, sBh + off);
                ldsm4(s, sBl + off);
                bh[nh * 2][0] = r[0]; bh[nh * 2][1] = r[2];
                bh[nh * 2 + 1][0] = r[1]; bh[nh * 2 + 1][1] = r[3];
                bl[nh * 2][0] = s[0]; bl[nh * 2][1] = s[2];
                bl[nh * 2 + 1][0] = s[1]; bl[nh * 2 + 1][1] = s[3];
            }
            // term-pass order: consecutive MMAs hit DIFFERENT accumulators
            #pragma unroll
            for (int mf = 0; mf < 4; mf++)
                #pragma unroll
                for (int nf = 0; nf < 4; nf++)
                    mma16816(acc[mf][nf], ah[mf], bh[nf]);
            #pragma unroll
            for (int mf = 0; mf < 4; mf++)
                #pragma unroll
                for (int nf = 0; nf < 4; nf++)
                    mma16816(acc[mf][nf], ah[mf], bl[nf]);
            #pragma unroll
            for (int mf = 0; mf < 4; mf++)
                #pragma unroll
                for (int nf = 0; nf < 4; nf++)
                    mma16816(acc[mf][nf], al[mf], bh[nf]);
        }
        __syncthreads();
    }

    // ---- epilogue ----
    const int rr = lane >> 2;
    const int cc = (lane & 3) * 2;
    #pragma unroll
    for (int mf = 0; mf < 4; mf++) {
        #pragma unroll
        for (int half = 0; half < 2; half++) {
            long grow = outRow0 + m0 + mf * 16 + rr + half * 8;
            float invd = (EPI == 2) ? (1.0f / denom[grow]) : 0.0f;
            #pragma unroll
            for (int nf = 0; nf < 4; nf++) {
                int gcol = colBlk + n0 + nf * 8 + cc;
                size_t gi = (size_t)grow * DD + gcol;
                float v0 = acc[mf][nf][half * 2 + 0];
                float v1 = acc[mf][nf][half * 2 + 1];
                if (EPI == 1) {
                    float2 xv = *reinterpret_cast<const float2*>(&Xadd[gi]);
                    v0 += xv.x; v1 += xv.y;
                    __half h0 = __float2half_rn(v0), h1 = __float2half_rn(v1);
                    __half l0 = __float2half_rn(v0 - __half2float(h0));
                    __half l1 = __float2half_rn(v1 - __half2float(h1));
                    *reinterpret_cast<__half2*>(&OutH[gi]) = __halves2half2(h0, h1);
                    *reinterpret_cast<__half2*>(&OutL[gi]) = __halves2half2(l0, l1);
                } else {
                    float2 bv = *reinterpret_cast<const float2*>(&bias[gcol]);
                    float2 o;
                    o.x = fmaxf((v0 + 2.0f * bv.x) * invd, 0.0f);
                    o.y = fmaxf((v1 + 2.0f * bv.y) * invd, 0.0f);
                    *reinterpret_cast<float2*>(&OutF[gi]) = o;
                }
            }
        }
    }
}

// ---------------- LayerNorm ----------------
__global__ void ln_kernel(const float* __restrict__ X, const float* __restrict__ g,
                          const float* __restrict__ b, float* __restrict__ out) {
    __shared__ float sh[32];
    const int row = blockIdx.x;
    const float* p = X + (size_t)row * DD;
    const int tid = threadIdx.x;
    float v0 = p[tid];
    float v1 = p[tid + 256];
    float mu = block_reduce_sum(v0 + v1, sh) * (1.0f / DD);
    float d0 = v0 - mu, d1 = v1 - mu;
    float var = block_reduce_sum(d0 * d0 + d1 * d1, sh) * (1.0f / DD);
    float r = rsqrtf(var + LN_EPS);
    out[(size_t)row * DD + tid] = d0 * r * g[tid] + b[tid];
    out[(size_t)row * DD + tid + 256] = d1 * r * g[tid + 256] + b[tid + 256];
}

__global__ void mask_kernel(const float* __restrict__ denom, const float* __restrict__ colsum,
                            float* __restrict__ out, int count) {
    int i = blockIdx.x * blockDim.x + threadIdx.x;
    if (i >= count) return;
    if (i < BB * NN) {
        float rs = denom[i] - 1.0f;
        out[i] = ((rs + colsum[i]) == 0.0f) ? 1.0f : 0.0f;
    } else {
        out[i] = 0.0f;
    }
}

// ---------------- launch ----------------
#define GEMM_SMEM (2 * STAGE_BYTES)

extern "C" void kernel_launch(void* const* d_in, const int* in_sizes, int n_in,
                              void* d_out, int out_size) {
    const float* adj = (const float*)d_in[0];
    const float* emb = (const float*)d_in[1];
    const float* W0w = (const float*)d_in[3];
    const float* W0b = (const float*)d_in[4];
    const float* W1w = (const float*)d_in[5];
    const float* W1b = (const float*)d_in[6];
    const float* lng = (const float*)d_in[7];
    const float* lnb = (const float*)d_in[8];
    float* out = (float*)d_out;

    float *denom, *colsum, *x;
    __half *adjh, *adjl, *xth, *xtl, *yh, *yl, *w0h, *w0l, *w1h, *w1l;
    cudaGetSymbolAddress((void**)&denom, g_denom);
    cudaGetSymbolAddress((void**)&colsum, g_colsum);
    cudaGetSymbolAddress((void**)&x, g_x);
    cudaGetSymbolAddress((void**)&adjh, g_adj_h);
    cudaGetSymbolAddress((void**)&adjl, g_adj_l);
    cudaGetSymbolAddress((void**)&xth, g_xT_h);
    cudaGetSymbolAddress((void**)&xtl, g_xT_l);
    cudaGetSymbolAddress((void**)&yh, g_y_h);
    cudaGetSymbolAddress((void**)&yl, g_y_l);
    cudaGetSymbolAddress((void**)&w0h, g_W0_h);
    cudaGetSymbolAddress((void**)&w0l, g_W0_l);
    cudaGetSymbolAddress((void**)&w1h, g_W1_h);
    cudaGetSymbolAddress((void**)&w1l, g_W1_l);

    cudaFuncSetAttribute(gemm_hmma<1024, 1>, cudaFuncAttributeMaxDynamicSharedMemorySize, GEMM_SMEM);
    cudaFuncSetAttribute(gemm_hmma<512, 2>, cudaFuncAttributeMaxDynamicSharedMemorySize, GEMM_SMEM);

    // fused adj pass (zero colsum first)
    zero_kernel<<<(BB * NN + 255) / 256, 256>>>(colsum, BB * NN);
    adj_pass_kernel<<<dim3(8, BB), 256>>>(adj, denom, colsum, adjh, adjl);

    {
        int w4 = (DD * DD) / 4;
        split_kernel<<<(w4 + 255) / 256, 256>>>(W0w, w0h, w0l, w4);
        split_kernel<<<(w4 + 255) / 256, 256>>>(W1w, w1h, w1l, w4);
    }

    dim3 tg(DD / 32, NN / 32, BB);
    dim3 tb(32, 8);
    dim3 g1(DD / 128, NN / 128, BB);
    dim3 g2(DD / 128, (BB * NN) / 128, 1);

    // layer 0
    transpose_split<<<tg, tb>>>(emb, xth, xtl);
    gemm_hmma<1024, 1><<<g1, 256, GEMM_SMEM>>>(adjh, adjl, xth, xtl, emb, yh, yl,
                                               nullptr, nullptr, nullptr);
    gemm_hmma<512, 2><<<g2, 256, GEMM_SMEM>>>(yh, yl, w0h, w0l, nullptr, nullptr, nullptr,
                                              W0b, denom, x);
    // layer 1
    transpose_split<<<tg, tb>>>(x, xth, xtl);
    gemm_hmma<1024, 1><<<g1, 256, GEMM_SMEM>>>(adjh, adjl, xth, xtl, x, yh, yl,
                                               nullptr, nullptr, nullptr);
    gemm_hmma<512, 2><<<g2, 256, GEMM_SMEM>>>(yh, yl, w1h, w1l, nullptr, nullptr, nullptr,
                                              W1b, denom, x);

    ln_kernel<<<BB * NN, 256>>>(x, lng, lnb, out);

    int extra = out_size - BB * NN * DD;
    if (extra > 0) {
        mask_kernel<<<(extra + 255) / 256, 256>>>(denom, colsum,
                                                  out + (size_t)BB * NN * DD, extra);
    }
}